// round 11
// baseline (speedup 1.0000x reference)
#include <cuda_runtime.h>

typedef unsigned long long u64;

#define B_  512
#define T_  512
#define F_  13
#define H_  128
#define NT  512

// 134MB scratch: xp[(b*T + t)*H + j] = x@W_ih^T + b_ih + b_hh
__device__ float g_xp[(size_t)B_ * T_ * H_];

__device__ __forceinline__ u64 fma2(u64 a, u64 b, u64 c) {
    u64 d;
    asm("fma.rn.f32x2 %0, %1, %2, %3;" : "=l"(d) : "l"(a), "l"(b), "l"(c));
    return d;
}
__device__ __forceinline__ float f2sum(u64 a) {
    float lo, hi;
    asm("mov.b64 {%0, %1}, %2;" : "=f"(lo), "=f"(hi) : "l"(a));
    return lo + hi;
}
// tanh(x) = 1 - 2/(1+e^{2x}); abs err ~1e-7, inf-safe.
__device__ __forceinline__ float tanh_fast(float x) {
    float e = __expf(2.f * x);
    return 1.f - __fdividef(2.f, 1.f + e);
}
__device__ __forceinline__ float sigmoid_fast(float s) {
    return __fdividef(1.f, 1.f + __expf(-s));
}

// ---------------------------------------------------------------------------
// Kernel 1: xp precompute (validated R9/R10). 256 threads / 256 (b,t) rows.
// ---------------------------------------------------------------------------
__global__ void __launch_bounds__(256, 2) xp_kernel(
    const float* __restrict__ x,
    const float* __restrict__ W_ih,
    const float* __restrict__ b_ih,
    const float* __restrict__ b_hh)
{
    __shared__ float xs[256 * 14];
    const int tid = threadIdx.x;
    const size_t rowbase = (size_t)blockIdx.x * 256;

    for (int i = tid; i < 256 * F_; i += 256) {
        int r = i / F_, f = i - r * F_;
        xs[r * 14 + f] = x[rowbase * F_ + i];
    }
    __syncthreads();

    const int j    = tid & 127;
    const int half = tid >> 7;
    float w[F_];
#pragma unroll
    for (int f = 0; f < F_; f++) w[f] = __ldg(W_ih + j * F_ + f);
    const float bias = __ldg(b_ih + j) + __ldg(b_hh + j);

    const int r0 = half * 128;
    for (int r = 0; r < 128; r++) {
        const float* xr = xs + (r0 + r) * 14;
        float acc = bias;
#pragma unroll
        for (int f = 0; f < F_; f++) acc = fmaf(xr[f], w[f], acc);
        g_xp[(rowbase + r0 + r) * H_ + j] = acc;
    }
}

// ---------------------------------------------------------------------------
// Kernel 2: fused persistent scan + fc head.
// 128 CTAs x 512 threads (4 warps/SMSP), 4 batch rows per CTA,
// ONE __syncthreads per step, <=128 regs/thread.
//
// Rec (tid 0..255): thread (jj = tid>>1, kh = tid&1) holds ONE W_hh row
//   k-half (64 f32 regs); partial dots for all 4 rows (128 fma2); partner
//   lane^1 swap via shfl_xor(1); + staged xp from Xp[cur]; tanh; STS its
//   2 rows into Hs[cur^1]. No global loads in the loop.
// FC (tid 256..511): thread (o = ft>>2, q = ft&3) holds a quarter fc1 row
//   (32 regs); quarter dots on h(t) = Hs[cur] (64 fma2); shfl merges;
//   relu*fc2_w; o-reduce; lane0 -> red[cur^1][warp].
//   xp staging pipeline (the R10 fix): STS of xc (LDG'd one full iteration
//   earlier) at the TOP of the iteration, then LDG xn = xp(t+2) with a whole
//   iteration of slack before its STS -> DRAM latency never touches the
//   barrier path.
// ---------------------------------------------------------------------------
__global__ void __launch_bounds__(NT, 1) rnn_fused(
    const float* __restrict__ W_hh,
    const float* __restrict__ fc1_w,
    const float* __restrict__ fc1_b,
    const float* __restrict__ fc2_w,
    const float* __restrict__ fc2_b,
    float* __restrict__ out)
{
    __shared__ __align__(16) float Hs[2][4 * H_];   // double-buffered h
    __shared__ __align__(16) float Xp[2][4 * H_];   // double-buffered xp tile
    __shared__ float red[2][8][4];                  // [buf][fc warp][row]

    const int tid  = threadIdx.x;
    const int row0 = blockIdx.x * 4;

    // ---- init: zero h(0), stage xp(0) ----
    {
        const int r = tid >> 7, j = tid & 127;
        Hs[0][r * H_ + j] = 0.f;
        Xp[0][r * H_ + j] = g_xp[((size_t)(row0 + r) * T_) * H_ + j];
    }
    __syncthreads();

    int cur = 0;

    if (tid < 256) {
        // =================== RECURRENCE ===================
        const int jj   = tid >> 1;       // 0..127
        const int kh   = tid & 1;        // k-half
        const int koff = kh * 64;
        const int r0   = 2 * kh,     r1 = 2 * kh + 1;   // rows finalized here
        const int o0   = 2 - 2 * kh, o1 = 3 - 2 * kh;   // partner's rows

        u64 w[32];   // 64 floats: W_hh[jj][koff .. koff+64)
        {
            const ulonglong2* wrow =
                (const ulonglong2*)(W_hh + (size_t)jj * H_ + koff);
#pragma unroll
            for (int m = 0; m < 16; m++) {
                ulonglong2 v = wrow[m];
                w[2 * m] = v.x; w[2 * m + 1] = v.y;
            }
        }

        for (int t = 0; t < T_; t++) {
            const float* Hrd = Hs[cur];
            float*       Hwr = Hs[cur ^ 1];
            const float* Xr  = Xp[cur];

            u64 a0[4], a1[4];
#pragma unroll
            for (int r = 0; r < 4; r++) { a0[r] = 0ull; a1[r] = 0ull; }

#pragma unroll
            for (int m = 0; m < 16; m++) {
                ulonglong2 h0 = *(const ulonglong2*)(Hrd + 0 * H_ + koff + 4 * m);
                ulonglong2 h1 = *(const ulonglong2*)(Hrd + 1 * H_ + koff + 4 * m);
                ulonglong2 h2 = *(const ulonglong2*)(Hrd + 2 * H_ + koff + 4 * m);
                ulonglong2 h3 = *(const ulonglong2*)(Hrd + 3 * H_ + koff + 4 * m);
                a0[0] = fma2(h0.x, w[2 * m], a0[0]);
                a0[1] = fma2(h1.x, w[2 * m], a0[1]);
                a0[2] = fma2(h2.x, w[2 * m], a0[2]);
                a0[3] = fma2(h3.x, w[2 * m], a0[3]);
                a1[0] = fma2(h0.y, w[2 * m + 1], a1[0]);
                a1[1] = fma2(h1.y, w[2 * m + 1], a1[1]);
                a1[2] = fma2(h2.y, w[2 * m + 1], a1[2]);
                a1[3] = fma2(h3.y, w[2 * m + 1], a1[3]);
            }

            float own_s0 = f2sum(a0[r0]) + f2sum(a1[r0]);
            float own_s1 = f2sum(a0[r1]) + f2sum(a1[r1]);
            float q0 = f2sum(a0[o0]) + f2sum(a1[o0]);
            float q1 = f2sum(a0[o1]) + f2sum(a1[o1]);
            // partner (lane^1) holds the other k-half of MY rows (symmetric)
            float e0 = __shfl_xor_sync(0xffffffffu, q0, 1);
            float e1 = __shfl_xor_sync(0xffffffffu, q1, 1);

            Hwr[r0 * H_ + jj] = tanh_fast(own_s0 + e0 + Xr[r0 * H_ + jj]);
            Hwr[r1 * H_ + jj] = tanh_fast(own_s1 + e1 + Xr[r1 * H_ + jj]);

            __syncthreads();
            cur ^= 1;
        }
        __syncthreads();    // pairs with fc's t = T_ iteration
    } else {
        // =================== FC HEAD + xp staging ===================
        const int ft   = tid - 256;      // 0..255
        const int o    = ft >> 2;        // 0..63
        const int q    = ft & 3;         // quarter
        const int wloc = ft >> 5;        // 0..7 (fc warp)
        const int lane = ft & 31;
        const int qoff = q * 32;

        u64 fw[16];  // 32 floats: fc1_w[o][qoff .. qoff+32)
        {
            const ulonglong2* fr =
                (const ulonglong2*)(fc1_w + (size_t)o * H_ + qoff);
#pragma unroll
            for (int m = 0; m < 8; m++) {
                ulonglong2 v = fr[m];
                fw[2 * m] = v.x; fw[2 * m + 1] = v.y;
            }
        }
        const float b1 = __ldg(fc1_b + o);
        const float w2 = __ldg(fc2_w + o);
        const float b2 = __ldg(fc2_b);

        // xp staging: thread ft covers (row rx, cols {jx, jx+64}).
        const int jx = ft & 63;
        const int rx = ft >> 6;
        const float* xsrc =
            g_xp + (((size_t)(row0 + rx) * T_) + 2) * H_ + jx;  // -> xp(t+2)

        // carry registers: xc = xp(t+1) (STS'd at iter t), loaded at iter t-1
        float xc0 = 0.f, xc1 = 0.f;
        if (T_ > 1) {
            const float* p1 =
                g_xp + (((size_t)(row0 + rx) * T_) + 1) * H_ + jx;
            xc0 = __ldg(p1);
            xc1 = __ldg(p1 + 64);
        }

        for (int t = 0; t <= T_; t++) {
            // (a) emit out index t-2 (combined at iter t-1)
            if (t >= 2 && ft < 4) {
                const int r = ft;
                float s = b2;
#pragma unroll
                for (int wv = 0; wv < 8; wv++) s += red[cur][wv][r];
                out[(size_t)(row0 + r) * T_ + (t - 2)] = sigmoid_fast(s);
            }

            // (b) STS xp(t+1) from long-ready regs (consumed by rec at t+1)
            if (t + 1 < T_) {
                Xp[cur ^ 1][rx * H_ + jx]      = xc0;
                Xp[cur ^ 1][rx * H_ + jx + 64] = xc1;
            }

            // (c) issue LDG xp(t+2) — a full iteration before its STS
            float xn0 = 0.f, xn1 = 0.f;
            if (t + 2 < T_) {
                xn0 = __ldg(xsrc);
                xn1 = __ldg(xsrc + 64);
                xsrc += H_;
            }

            // (d) fc quarter-dots on h(t) = Hs[cur]
            if (t >= 1) {
                const float* Hrd = Hs[cur];
                u64 c0[4], c1[4];
#pragma unroll
                for (int r = 0; r < 4; r++) { c0[r] = 0ull; c1[r] = 0ull; }
#pragma unroll
                for (int m = 0; m < 8; m++) {
#pragma unroll
                    for (int r = 0; r < 4; r++) {
                        ulonglong2 hv =
                            *(const ulonglong2*)(Hrd + r * H_ + qoff + 4 * m);
                        c0[r] = fma2(hv.x, fw[2 * m],     c0[r]);
                        c1[r] = fma2(hv.y, fw[2 * m + 1], c1[r]);
                    }
                }
                float y[4];
#pragma unroll
                for (int r = 0; r < 4; r++) {
                    float d = f2sum(c0[r]) + f2sum(c1[r]);
                    d += __shfl_xor_sync(0xffffffffu, d, 1);
                    d += __shfl_xor_sync(0xffffffffu, d, 2);
                    y[r] = fmaxf(d + b1, 0.f) * w2;
                }
#pragma unroll
                for (int off = 4; off <= 16; off <<= 1) {
#pragma unroll
                    for (int r = 0; r < 4; r++)
                        y[r] += __shfl_xor_sync(0xffffffffu, y[r], off);
                }
                if (lane == 0) {
#pragma unroll
                    for (int r = 0; r < 4; r++) red[cur ^ 1][wloc][r] = y[r];
                }
            }

            __syncthreads();
            // (f) rotate carry
            xc0 = xn0; xc1 = xn1;
            cur ^= 1;
        }

        // final output index T_-1 (combined at iter T_)
        if (ft < 4) {
            const int r = ft;
            float s = b2;
#pragma unroll
            for (int wv = 0; wv < 8; wv++) s += red[cur][wv][r];
            out[(size_t)(row0 + r) * T_ + (T_ - 1)] = sigmoid_fast(s);
        }
    }
}

// ---------------------------------------------------------------------------

extern "C" void kernel_launch(void* const* d_in, const int* in_sizes, int n_in,
                              void* d_out, int out_size)
{
    const float* x     = (const float*)d_in[0];
    const float* W_ih  = (const float*)d_in[1];
    const float* W_hh  = (const float*)d_in[2];
    const float* b_ih  = (const float*)d_in[3];
    const float* b_hh  = (const float*)d_in[4];
    const float* fc1_w = (const float*)d_in[5];
    const float* fc1_b = (const float*)d_in[6];
    const float* fc2_w = (const float*)d_in[7];
    const float* fc2_b = (const float*)d_in[8];
    float* out = (float*)d_out;

    xp_kernel<<<(B_ * T_) / 256, 256>>>(x, W_ih, b_ih, b_hh);
    rnn_fused<<<128, NT>>>(W_hh, fc1_w, fc1_b, fc2_w, fc2_b, out);
}

// round 13
// speedup vs baseline: 2.7943x; 2.7943x over previous
#include <cuda_runtime.h>

typedef unsigned long long u64;

#define B_  512
#define T_  512
#define F_  13
#define H_  128
#define NT  256

// 134MB scratch: xp[(b*T + t)*H + j] = x@W_ih^T + b_ih + b_hh
__device__ float g_xp[(size_t)B_ * T_ * H_];

__device__ __forceinline__ u64 fma2(u64 a, u64 b, u64 c) {
    u64 d;
    asm("fma.rn.f32x2 %0, %1, %2, %3;" : "=l"(d) : "l"(a), "l"(b), "l"(c));
    return d;
}
__device__ __forceinline__ float f2sum(u64 a) {
    float lo, hi;
    asm("mov.b64 {%0, %1}, %2;" : "=f"(lo), "=f"(hi) : "l"(a));
    return lo + hi;
}
// tanh(x) = 1 - 2/(1+e^{2x}); abs err ~1e-7, inf-safe.
__device__ __forceinline__ float tanh_fast(float x) {
    float e = __expf(2.f * x);
    return 1.f - __fdividef(2.f, 1.f + e);
}
__device__ __forceinline__ float sigmoid_fast(float s) {
    return __fdividef(1.f, 1.f + __expf(-s));
}

// ---------------------------------------------------------------------------
// Kernel 1: xp precompute (validated R9/R10/R11). 256 threads / 256 rows.
// ---------------------------------------------------------------------------
__global__ void __launch_bounds__(256, 2) xp_kernel(
    const float* __restrict__ x,
    const float* __restrict__ W_ih,
    const float* __restrict__ b_ih,
    const float* __restrict__ b_hh)
{
    __shared__ float xs[256 * 14];
    const int tid = threadIdx.x;
    const size_t rowbase = (size_t)blockIdx.x * 256;

    for (int i = tid; i < 256 * F_; i += 256) {
        int r = i / F_, f = i - r * F_;
        xs[r * 14 + f] = x[rowbase * F_ + i];
    }
    __syncthreads();

    const int j    = tid & 127;
    const int half = tid >> 7;
    float w[F_];
#pragma unroll
    for (int f = 0; f < F_; f++) w[f] = __ldg(W_ih + j * F_ + f);
    const float bias = __ldg(b_ih + j) + __ldg(b_hh + j);

    const int r0 = half * 128;
    for (int r = 0; r < 128; r++) {
        const float* xr = xs + (r0 + r) * 14;
        float acc = bias;
#pragma unroll
        for (int f = 0; f < F_; f++) acc = fmaf(xr[f], w[f], acc);
        g_xp[(rowbase + r0 + r) * H_ + j] = acc;
    }
}

// ---------------------------------------------------------------------------
// Kernel 2: fused persistent scan + fc head.
// == R8 (683us, validated numerics) minus the input projection ==
// 128 CTAs x 256 threads, 4 batch rows per CTA, ONE __syncthreads per step.
//
// Rec (tid 0..127): thread (jj = tid>>1, kh = tid&1) holds W_hh rows
//   {jj, jj+64} over k-half [64kh,+64) -> 128 weight regs. 256 fma2/step.
//   xp(t) comes from the smem tile Xp[cur] (4 conflict-free LDS.32); NO
//   global loads and NO inproj in the rec branch -> ~190-210 regs, no spill.
//   Cross-half partials merge via shfl_xor(1); tanh; STS into Hs[cur^1].
// FC (tid 128..255): as R8 (validated): thread (kh2 = ft&1, oo = (ft>>1)&31,
//   rp = ft>>6) holds fc1_w rows {oo, oo+32} over a k-half; dots on
//   h(t) = Hs[cur] for rows {2rp, 2rp+1}; k-merge shfl, relu*fc2_w, bfly
//   2..16; lane0 -> red[cur^1]; 4 threads emit sigmoid one iteration later.
//   ALSO stages xp: carries xc[4] in regs (loaded a full iteration early),
//   STS at top of iteration into Xp[cur^1], then LDG xp(t+2).
// ---------------------------------------------------------------------------
__global__ void __launch_bounds__(NT, 1) rnn_fused(
    const float* __restrict__ W_hh,
    const float* __restrict__ fc1_w,
    const float* __restrict__ fc1_b,
    const float* __restrict__ fc2_w,
    const float* __restrict__ fc2_b,
    float* __restrict__ out)
{
    __shared__ __align__(16) float Hs[2][4 * H_];   // double-buffered h
    __shared__ __align__(16) float Xp[2][4 * H_];   // double-buffered xp tile
    __shared__ float2 red[2][2][2];                 // [buf][rp][oohigh]

    const int tid  = threadIdx.x;
    const int row0 = blockIdx.x * 4;

    // ---- init: zero h, stage xp(0) ----
    for (int i = tid; i < 2 * 4 * H_; i += NT) ((float*)Hs)[i] = 0.f;
    {
        // Xp[0][idx], idx = r*H_ + j
        int i0 = tid;         // covers 0..255
        int i1 = tid + 256;   // covers 256..511
        int r0i = i0 >> 7, j0i = i0 & 127;
        int r1i = i1 >> 7, j1i = i1 & 127;
        Xp[0][i0] = g_xp[((size_t)(row0 + r0i) * T_) * H_ + j0i];
        Xp[0][i1] = g_xp[((size_t)(row0 + r1i) * T_) * H_ + j1i];
    }
    __syncthreads();

    int cur = 0;

    if (tid < 128) {
        // =================== RECURRENCE ===================
        const int jj   = tid >> 1;       // j rows {jj, jj+64}
        const int kh   = tid & 1;        // k-half
        const int koff = kh * 64;
        const int r0   = 2 * kh,     r1 = 2 * kh + 1;   // owned batch rows
        const int o0   = 2 - 2 * kh, o1 = 3 - 2 * kh;   // partner's rows

        u64 wA[32], wB[32];
        {
            const ulonglong2* ra =
                (const ulonglong2*)(W_hh + (size_t)jj * H_ + koff);
            const ulonglong2* rb =
                (const ulonglong2*)(W_hh + (size_t)(jj + 64) * H_ + koff);
#pragma unroll
            for (int m = 0; m < 16; m++) {
                ulonglong2 va = ra[m], vb = rb[m];
                wA[2 * m] = va.x; wA[2 * m + 1] = va.y;
                wB[2 * m] = vb.x; wB[2 * m + 1] = vb.y;
            }
        }

        for (int t = 0; t <= T_; t++) {
            if (t < T_) {
                const float* Hrd = Hs[cur];
                float*       Hwr = Hs[cur ^ 1];
                const float* Xr  = Xp[cur];

                // xp terms for the 4 outputs this thread finalizes
                float xA0 = Xr[r0 * H_ + jj];
                float xA1 = Xr[r1 * H_ + jj];
                float xB0 = Xr[r0 * H_ + jj + 64];
                float xB1 = Xr[r1 * H_ + jj + 64];

                u64 aA[4], aB[4];
#pragma unroll
                for (int r = 0; r < 4; r++) { aA[r] = 0ull; aB[r] = 0ull; }

                // recurrent partials over this k-half; each 16B load feeds 2 j
#pragma unroll
                for (int m = 0; m < 16; m++) {
                    ulonglong2 h0 = *(const ulonglong2*)(Hrd + 0 * H_ + koff + 4 * m);
                    ulonglong2 h1 = *(const ulonglong2*)(Hrd + 1 * H_ + koff + 4 * m);
                    ulonglong2 h2 = *(const ulonglong2*)(Hrd + 2 * H_ + koff + 4 * m);
                    ulonglong2 h3 = *(const ulonglong2*)(Hrd + 3 * H_ + koff + 4 * m);
                    aA[0] = fma2(h0.x, wA[2 * m], aA[0]);
                    aA[1] = fma2(h1.x, wA[2 * m], aA[1]);
                    aA[2] = fma2(h2.x, wA[2 * m], aA[2]);
                    aA[3] = fma2(h3.x, wA[2 * m], aA[3]);
                    aB[0] = fma2(h0.x, wB[2 * m], aB[0]);
                    aB[1] = fma2(h1.x, wB[2 * m], aB[1]);
                    aB[2] = fma2(h2.x, wB[2 * m], aB[2]);
                    aB[3] = fma2(h3.x, wB[2 * m], aB[3]);
                    aA[0] = fma2(h0.y, wA[2 * m + 1], aA[0]);
                    aA[1] = fma2(h1.y, wA[2 * m + 1], aA[1]);
                    aA[2] = fma2(h2.y, wA[2 * m + 1], aA[2]);
                    aA[3] = fma2(h3.y, wA[2 * m + 1], aA[3]);
                    aB[0] = fma2(h0.y, wB[2 * m + 1], aB[0]);
                    aB[1] = fma2(h1.y, wB[2 * m + 1], aB[1]);
                    aB[2] = fma2(h2.y, wB[2 * m + 1], aB[2]);
                    aB[3] = fma2(h3.y, wB[2 * m + 1], aB[3]);
                }

                float pA0 = f2sum(aA[r0]), pA1 = f2sum(aA[r1]);
                float pB0 = f2sum(aB[r0]), pB1 = f2sum(aB[r1]);
                float qA0 = f2sum(aA[o0]), qA1 = f2sum(aA[o1]);
                float qB0 = f2sum(aB[o0]), qB1 = f2sum(aB[o1]);
                // partner (lane^1) holds the other k-half of MY rows
                float eA0 = __shfl_xor_sync(0xffffffffu, qA0, 1);
                float eA1 = __shfl_xor_sync(0xffffffffu, qA1, 1);
                float eB0 = __shfl_xor_sync(0xffffffffu, qB0, 1);
                float eB1 = __shfl_xor_sync(0xffffffffu, qB1, 1);

                Hwr[r0 * H_ + jj]      = tanh_fast(pA0 + eA0 + xA0);
                Hwr[r1 * H_ + jj]      = tanh_fast(pA1 + eA1 + xA1);
                Hwr[r0 * H_ + jj + 64] = tanh_fast(pB0 + eB0 + xB0);
                Hwr[r1 * H_ + jj + 64] = tanh_fast(pB1 + eB1 + xB1);
            }
            __syncthreads();
            cur ^= 1;
        }
    } else {
        // =================== FC HEAD + xp staging ===================
        const int ft    = tid - 128;       // 0..127
        const int oo    = (ft >> 1) & 31;  // o rows {oo, oo+32}
        const int rp    = ft >> 6;         // batch rows {2rp, 2rp+1}
        const int lane  = ft & 31;
        const int ooh   = (ft >> 5) & 1;
        const int koff2 = (ft & 1) * 64;

        u64 fwA[32], fwB[32];
        {
            const ulonglong2* ra =
                (const ulonglong2*)(fc1_w + (size_t)oo * H_ + koff2);
            const ulonglong2* rb =
                (const ulonglong2*)(fc1_w + (size_t)(oo + 32) * H_ + koff2);
#pragma unroll
            for (int m = 0; m < 16; m++) {
                ulonglong2 va = ra[m], vb = rb[m];
                fwA[2 * m] = va.x; fwA[2 * m + 1] = va.y;
                fwB[2 * m] = vb.x; fwB[2 * m + 1] = vb.y;
            }
        }
        const float b1A = __ldg(fc1_b + oo);
        const float b1B = __ldg(fc1_b + oo + 32);
        const float w2A = __ldg(fc2_w + oo);
        const float w2B = __ldg(fc2_w + oo + 32);
        const float b2  = __ldg(fc2_b);

        // xp staging: thread ft owns column jcol for all 4 rows.
        const int jcol = ft;     // 0..127
        const float* xs0 = g_xp + ((size_t)(row0 + 0) * T_ + 2) * H_ + jcol;
        const float* xs1 = g_xp + ((size_t)(row0 + 1) * T_ + 2) * H_ + jcol;
        const float* xs2 = g_xp + ((size_t)(row0 + 2) * T_ + 2) * H_ + jcol;
        const float* xs3 = g_xp + ((size_t)(row0 + 3) * T_ + 2) * H_ + jcol;
        // carry: xc[r] = xp(r, t+1) — STS'd at iter t, loaded one iter early
        float xc0 = __ldg(g_xp + ((size_t)(row0 + 0) * T_ + 1) * H_ + jcol);
        float xc1 = __ldg(g_xp + ((size_t)(row0 + 1) * T_ + 1) * H_ + jcol);
        float xc2 = __ldg(g_xp + ((size_t)(row0 + 2) * T_ + 1) * H_ + jcol);
        float xc3 = __ldg(g_xp + ((size_t)(row0 + 3) * T_ + 1) * H_ + jcol);

        for (int t = 0; t <= T_; t++) {
            // (a) emit out index t-2 (combined at iter t-1)
            if (t >= 2 && ft < 4) {
                const int r = ft;
                float2 v0 = red[cur][r >> 1][0];
                float2 v1 = red[cur][r >> 1][1];
                float s = (r & 1) ? (v0.y + v1.y) : (v0.x + v1.x);
                out[(size_t)(row0 + r) * T_ + (t - 2)] = sigmoid_fast(s + b2);
            }

            // (b) STS xp(t+1) from long-ready carry regs
            if (t + 1 < T_) {
                float* Xw = Xp[cur ^ 1];
                Xw[0 * H_ + jcol] = xc0;
                Xw[1 * H_ + jcol] = xc1;
                Xw[2 * H_ + jcol] = xc2;
                Xw[3 * H_ + jcol] = xc3;
            }
            // (c) LDG xp(t+2) into the carry — a full iteration of slack
            if (t + 2 < T_) {
                xc0 = __ldg(xs0); xs0 += H_;
                xc1 = __ldg(xs1); xs1 += H_;
                xc2 = __ldg(xs2); xs2 += H_;
                xc3 = __ldg(xs3); xs3 += H_;
            }

            // (d) fc dots on h(t) = Hs[cur]
            if (t >= 1) {
                const float* Hrd = Hs[cur];
                const float* h0p = Hrd + (2 * rp) * H_ + koff2;
                const float* h1p = Hrd + (2 * rp + 1) * H_ + koff2;

                u64 q00 = 0ull, q01 = 0ull, q10 = 0ull, q11 = 0ull;
#pragma unroll
                for (int m = 0; m < 16; m++) {
                    ulonglong2 hv0 = *(const ulonglong2*)(h0p + 4 * m);
                    ulonglong2 hv1 = *(const ulonglong2*)(h1p + 4 * m);
                    q00 = fma2(hv0.x, fwA[2 * m], q00);
                    q01 = fma2(hv0.x, fwB[2 * m], q01);
                    q10 = fma2(hv1.x, fwA[2 * m], q10);
                    q11 = fma2(hv1.x, fwB[2 * m], q11);
                    q00 = fma2(hv0.y, fwA[2 * m + 1], q00);
                    q01 = fma2(hv0.y, fwB[2 * m + 1], q01);
                    q10 = fma2(hv1.y, fwA[2 * m + 1], q10);
                    q11 = fma2(hv1.y, fwB[2 * m + 1], q11);
                }
                float d00 = f2sum(q00), d01 = f2sum(q01);
                float d10 = f2sum(q10), d11 = f2sum(q11);
                // merge k-halves (partner = lane^1, same oo/rp)
                d00 += __shfl_xor_sync(0xffffffffu, d00, 1);
                d01 += __shfl_xor_sync(0xffffffffu, d01, 1);
                d10 += __shfl_xor_sync(0xffffffffu, d10, 1);
                d11 += __shfl_xor_sync(0xffffffffu, d11, 1);

                float z0 = fmaxf(d00 + b1A, 0.f) * w2A
                         + fmaxf(d01 + b1B, 0.f) * w2B;
                float z1 = fmaxf(d10 + b1A, 0.f) * w2A
                         + fmaxf(d11 + b1B, 0.f) * w2B;
                // reduce over oo-bits (even/odd lane parities hold copies)
#pragma unroll
                for (int off = 2; off <= 16; off <<= 1) {
                    z0 += __shfl_xor_sync(0xffffffffu, z0, off);
                    z1 += __shfl_xor_sync(0xffffffffu, z1, off);
                }
                if (lane == 0)
                    red[cur ^ 1][rp][ooh] = make_float2(z0, z1);
            }

            __syncthreads();
            cur ^= 1;
        }

        // final output index T-1 (combined at iter T, after last barrier)
        if (ft < 4) {
            const int r = ft;
            float2 v0 = red[cur][r >> 1][0];
            float2 v1 = red[cur][r >> 1][1];
            float s = (r & 1) ? (v0.y + v1.y) : (v0.x + v1.x);
            out[(size_t)(row0 + r) * T_ + (T_ - 1)] = sigmoid_fast(s + b2);
        }
    }
}

// ---------------------------------------------------------------------------

extern "C" void kernel_launch(void* const* d_in, const int* in_sizes, int n_in,
                              void* d_out, int out_size)
{
    const float* x     = (const float*)d_in[0];
    const float* W_ih  = (const float*)d_in[1];
    const float* W_hh  = (const float*)d_in[2];
    const float* b_ih  = (const float*)d_in[3];
    const float* b_hh  = (const float*)d_in[4];
    const float* fc1_w = (const float*)d_in[5];
    const float* fc1_b = (const float*)d_in[6];
    const float* fc2_w = (const float*)d_in[7];
    const float* fc2_b = (const float*)d_in[8];
    float* out = (float*)d_out;

    xp_kernel<<<(B_ * T_) / 256, 256>>>(x, W_ih, b_ih, b_hh);
    rnn_fused<<<128, NT>>>(W_hh, fc1_w, fc1_b, fc2_w, fc2_b, out);
}

// round 16
// speedup vs baseline: 2.8266x; 1.0116x over previous
#include <cuda_runtime.h>

typedef unsigned long long u64;

#define B_  512
#define T_  512
#define F_  13
#define H_  128
#define NT  256

// 134MB scratch: xp[(b*T + t)*H + j] = x@W_ih^T + b_ih + b_hh
__device__ float g_xp[(size_t)B_ * T_ * H_];

__device__ __forceinline__ u64 fma2(u64 a, u64 b, u64 c) {
    u64 d;
    asm("fma.rn.f32x2 %0, %1, %2, %3;" : "=l"(d) : "l"(a), "l"(b), "l"(c));
    return d;
}
__device__ __forceinline__ float f2sum(u64 a) {
    float lo, hi;
    asm("mov.b64 {%0, %1}, %2;" : "=f"(lo), "=f"(hi) : "l"(a));
    return lo + hi;
}
// tanh(x) = 1 - 2/(1+e^{2x}); abs err ~1e-7, inf-safe.
__device__ __forceinline__ float tanh_fast(float x) {
    float e = __expf(2.f * x);
    return 1.f - __fdividef(2.f, 1.f + e);
}
__device__ __forceinline__ float sigmoid_fast(float s) {
    return __fdividef(1.f, 1.f + __expf(-s));
}
__device__ __forceinline__ void bar_sync(int id, int cnt) {
    asm volatile("bar.sync %0, %1;" :: "r"(id), "r"(cnt) : "memory");
}
__device__ __forceinline__ void bar_arrive(int id, int cnt) {
    asm volatile("bar.arrive %0, %1;" :: "r"(id), "r"(cnt) : "memory");
}

// ---------------------------------------------------------------------------
// Kernel 1: xp precompute (validated R9..R13). 256 threads / 256 rows.
// ---------------------------------------------------------------------------
__global__ void __launch_bounds__(256, 2) xp_kernel(
    const float* __restrict__ x,
    const float* __restrict__ W_ih,
    const float* __restrict__ b_ih,
    const float* __restrict__ b_hh)
{
    __shared__ float xs[256 * 14];
    const int tid = threadIdx.x;
    const size_t rowbase = (size_t)blockIdx.x * 256;

    for (int i = tid; i < 256 * F_; i += 256) {
        int r = i / F_, f = i - r * F_;
        xs[r * 14 + f] = x[rowbase * F_ + i];
    }
    __syncthreads();

    const int j    = tid & 127;
    const int half = tid >> 7;
    float w[F_];
#pragma unroll
    for (int f = 0; f < F_; f++) w[f] = __ldg(W_ih + j * F_ + f);
    const float bias = __ldg(b_ih + j) + __ldg(b_hh + j);

    const int r0 = half * 128;
    for (int r = 0; r < 128; r++) {
        const float* xr = xs + (r0 + r) * 14;
        float acc = bias;
#pragma unroll
        for (int f = 0; f < F_; f++) acc = fmaf(xr[f], w[f], acc);
        g_xp[(rowbase + r0 + r) * H_ + j] = acc;
    }
}

// ---------------------------------------------------------------------------
// Kernel 2: fused persistent scan + fc head, producer-consumer decoupled with
// PHASE-SPLIT named barriers (no ID can be double-arrived between firings).
// 128 CTAs x 256 threads, 4 batch rows per CTA.
//
// rec = tid 128..255 (HIGH wids -> arbiter priority). fc = tid 0..127.
//   bar1 (128): rec-internal step barrier.
//   barH = ids {2,5}: "h(t+1) ready". rec ARRIVES barH[t&1] at end of iter t;
//         fc SYNCS barH[(n-1)&1] at top of iter n (pairs n = t+1).
//   barF = ids {3,6}: "fc(n) done". fc ARRIVES barF[n&1] at end of iter n;
//         rec SYNCS barF[(t-1)&1] for t>=2 (pairs n = t-1). Guards the
//         Hs[(t+1)&1] overwrite (fc n=t-1 finished reading it) and the
//         Xp[t&1] read (fc n=t-1 staged xp(t) into it).
//   bar4 (128): fc-internal (red combine before output emit).
// Phase-split safety: rec's next arrive on a given barH id is gated through
// barF <- fc's arrive <- fc's sync of that same barH id (and symmetrically
// for fc/barF), so every firing has exactly 128 rec + 128 fc arrivals.
// ---------------------------------------------------------------------------
__global__ void __launch_bounds__(NT, 1) rnn_fused(
    const float* __restrict__ W_hh,
    const float* __restrict__ fc1_w,
    const float* __restrict__ fc1_b,
    const float* __restrict__ fc2_w,
    const float* __restrict__ fc2_b,
    float* __restrict__ out)
{
    __shared__ __align__(16) float Hs[2][4 * H_];   // double-buffered h
    __shared__ __align__(16) float Xp[2][4 * H_];   // double-buffered xp tile
    __shared__ float2 red[2][2];                    // [rp][oohigh]

    const int tid  = threadIdx.x;
    const int row0 = blockIdx.x * 4;

    // ---- init: zero h(0), stage xp(0) and xp(1) ----
    for (int i = tid; i < 2 * 4 * H_; i += NT) ((float*)Hs)[i] = 0.f;
    {
        int i0 = tid, i1 = tid + 256;
        int r0i = i0 >> 7, j0i = i0 & 127;
        int r1i = i1 >> 7, j1i = i1 & 127;
        Xp[0][i0] = g_xp[((size_t)(row0 + r0i) * T_ + 0) * H_ + j0i];
        Xp[0][i1] = g_xp[((size_t)(row0 + r1i) * T_ + 0) * H_ + j1i];
        Xp[1][i0] = g_xp[((size_t)(row0 + r0i) * T_ + 1) * H_ + j0i];
        Xp[1][i1] = g_xp[((size_t)(row0 + r1i) * T_ + 1) * H_ + j1i];
    }
    __syncthreads();

    if (tid >= 128) {
        // =================== RECURRENCE (producer) ===================
        const int rt   = tid - 128;      // 0..127
        const int jj   = rt >> 1;        // j rows {jj, jj+64}
        const int kh   = rt & 1;         // k-half
        const int koff = kh * 64;
        const int r0   = 2 * kh,     r1 = 2 * kh + 1;   // owned batch rows
        const int o0   = 2 - 2 * kh, o1 = 3 - 2 * kh;   // partner's rows

        u64 wA[32], wB[32];
        {
            const ulonglong2* ra =
                (const ulonglong2*)(W_hh + (size_t)jj * H_ + koff);
            const ulonglong2* rb =
                (const ulonglong2*)(W_hh + (size_t)(jj + 64) * H_ + koff);
#pragma unroll
            for (int m = 0; m < 16; m++) {
                ulonglong2 va = ra[m], vb = rb[m];
                wA[2 * m] = va.x; wA[2 * m + 1] = va.y;
                wB[2 * m] = vb.x; wB[2 * m + 1] = vb.y;
            }
        }

        for (int t = 0; t < T_; t++) {
            const float* Hrd = Hs[t & 1];
            float*       Hwr = Hs[(t + 1) & 1];
            const float* Xr  = Xp[t & 1];

            u64 aA[4], aB[4];
#pragma unroll
            for (int r = 0; r < 4; r++) { aA[r] = 0ull; aB[r] = 0ull; }

            // recurrent partials over this k-half; each 16B load feeds 2 j
#pragma unroll
            for (int m = 0; m < 16; m++) {
                ulonglong2 h0 = *(const ulonglong2*)(Hrd + 0 * H_ + koff + 4 * m);
                ulonglong2 h1 = *(const ulonglong2*)(Hrd + 1 * H_ + koff + 4 * m);
                ulonglong2 h2 = *(const ulonglong2*)(Hrd + 2 * H_ + koff + 4 * m);
                ulonglong2 h3 = *(const ulonglong2*)(Hrd + 3 * H_ + koff + 4 * m);
                aA[0] = fma2(h0.x, wA[2 * m], aA[0]);
                aA[1] = fma2(h1.x, wA[2 * m], aA[1]);
                aA[2] = fma2(h2.x, wA[2 * m], aA[2]);
                aA[3] = fma2(h3.x, wA[2 * m], aA[3]);
                aB[0] = fma2(h0.x, wB[2 * m], aB[0]);
                aB[1] = fma2(h1.x, wB[2 * m], aB[1]);
                aB[2] = fma2(h2.x, wB[2 * m], aB[2]);
                aB[3] = fma2(h3.x, wB[2 * m], aB[3]);
                aA[0] = fma2(h0.y, wA[2 * m + 1], aA[0]);
                aA[1] = fma2(h1.y, wA[2 * m + 1], aA[1]);
                aA[2] = fma2(h2.y, wA[2 * m + 1], aA[2]);
                aA[3] = fma2(h3.y, wA[2 * m + 1], aA[3]);
                aB[0] = fma2(h0.y, wB[2 * m + 1], aB[0]);
                aB[1] = fma2(h1.y, wB[2 * m + 1], aB[1]);
                aB[2] = fma2(h2.y, wB[2 * m + 1], aB[2]);
                aB[3] = fma2(h3.y, wB[2 * m + 1], aB[3]);
            }

            float pA0 = f2sum(aA[r0]), pA1 = f2sum(aA[r1]);
            float pB0 = f2sum(aB[r0]), pB1 = f2sum(aB[r1]);
            float qA0 = f2sum(aA[o0]), qA1 = f2sum(aA[o1]);
            float qB0 = f2sum(aB[o0]), qB1 = f2sum(aB[o1]);
            // partner (lane^1) holds the other k-half of MY rows
            float eA0 = __shfl_xor_sync(0xffffffffu, qA0, 1);
            float eA1 = __shfl_xor_sync(0xffffffffu, qA1, 1);
            float eB0 = __shfl_xor_sync(0xffffffffu, qB0, 1);
            float eB1 = __shfl_xor_sync(0xffffffffu, qB1, 1);

            // wait for fc(t-1) done (t<2: buffers free / Xp init-staged)
            if (t >= 2) bar_sync(((t - 1) & 1) ? 3 : 6, 256);

            float xA0 = Xr[r0 * H_ + jj];
            float xA1 = Xr[r1 * H_ + jj];
            float xB0 = Xr[r0 * H_ + jj + 64];
            float xB1 = Xr[r1 * H_ + jj + 64];

            Hwr[r0 * H_ + jj]      = tanh_fast(pA0 + eA0 + xA0);
            Hwr[r1 * H_ + jj]      = tanh_fast(pA1 + eA1 + xA1);
            Hwr[r0 * H_ + jj + 64] = tanh_fast(pB0 + eB0 + xB0);
            Hwr[r1 * H_ + jj + 64] = tanh_fast(pB1 + eB1 + xB1);

            bar_arrive((t & 1) ? 5 : 2, 256);   // h(t+1) published
            bar_sync(1, 128);                   // rec-internal visibility
        }
    } else {
        // =================== FC HEAD (consumer) + xp staging ===================
        const int ft    = tid;             // 0..127
        const int oo    = (ft >> 1) & 31;  // o rows {oo, oo+32}
        const int rp    = ft >> 6;         // batch rows {2rp, 2rp+1}
        const int lane  = ft & 31;
        const int ooh   = (ft >> 5) & 1;
        const int koff2 = (ft & 1) * 64;

        u64 fwA[32], fwB[32];
        {
            const ulonglong2* ra =
                (const ulonglong2*)(fc1_w + (size_t)oo * H_ + koff2);
            const ulonglong2* rb =
                (const ulonglong2*)(fc1_w + (size_t)(oo + 32) * H_ + koff2);
#pragma unroll
            for (int m = 0; m < 16; m++) {
                ulonglong2 va = ra[m], vb = rb[m];
                fwA[2 * m] = va.x; fwA[2 * m + 1] = va.y;
                fwB[2 * m] = vb.x; fwB[2 * m + 1] = vb.y;
            }
        }
        const float b1A = __ldg(fc1_b + oo);
        const float b1B = __ldg(fc1_b + oo + 32);
        const float w2A = __ldg(fc2_w + oo);
        const float w2B = __ldg(fc2_w + oo + 32);
        const float b2  = __ldg(fc2_b);

        // xp staging: thread ft owns column jcol for all 4 rows.
        const int jcol = ft;
        const float* xs0 = g_xp + ((size_t)(row0 + 0) * T_ + 3) * H_ + jcol;
        const float* xs1 = g_xp + ((size_t)(row0 + 1) * T_ + 3) * H_ + jcol;
        const float* xs2 = g_xp + ((size_t)(row0 + 2) * T_ + 3) * H_ + jcol;
        const float* xs3 = g_xp + ((size_t)(row0 + 3) * T_ + 3) * H_ + jcol;
        // carry = xp(2): STS'd at n=1 (stages xp(n+1))
        float xc0 = __ldg(g_xp + ((size_t)(row0 + 0) * T_ + 2) * H_ + jcol);
        float xc1 = __ldg(g_xp + ((size_t)(row0 + 1) * T_ + 2) * H_ + jcol);
        float xc2 = __ldg(g_xp + ((size_t)(row0 + 2) * T_ + 2) * H_ + jcol);
        float xc3 = __ldg(g_xp + ((size_t)(row0 + 3) * T_ + 2) * H_ + jcol);

        for (int n = 1; n <= T_; n++) {
            bar_sync(((n - 1) & 1) ? 5 : 2, 256);   // h(n) ready in Hs[n&1]

            const float* Hrd = Hs[n & 1];
            const float* h0p = Hrd + (2 * rp) * H_ + koff2;
            const float* h1p = Hrd + (2 * rp + 1) * H_ + koff2;

            u64 q00 = 0ull, q01 = 0ull, q10 = 0ull, q11 = 0ull;
#pragma unroll
            for (int m = 0; m < 16; m++) {
                ulonglong2 hv0 = *(const ulonglong2*)(h0p + 4 * m);
                ulonglong2 hv1 = *(const ulonglong2*)(h1p + 4 * m);
                q00 = fma2(hv0.x, fwA[2 * m], q00);
                q01 = fma2(hv0.x, fwB[2 * m], q01);
                q10 = fma2(hv1.x, fwA[2 * m], q10);
                q11 = fma2(hv1.x, fwB[2 * m], q11);
                q00 = fma2(hv0.y, fwA[2 * m + 1], q00);
                q01 = fma2(hv0.y, fwB[2 * m + 1], q01);
                q10 = fma2(hv1.y, fwA[2 * m + 1], q10);
                q11 = fma2(hv1.y, fwB[2 * m + 1], q11);
            }
            float d00 = f2sum(q00), d01 = f2sum(q01);
            float d10 = f2sum(q10), d11 = f2sum(q11);
            // merge k-halves (partner = lane^1, same oo/rp)
            d00 += __shfl_xor_sync(0xffffffffu, d00, 1);
            d01 += __shfl_xor_sync(0xffffffffu, d01, 1);
            d10 += __shfl_xor_sync(0xffffffffu, d10, 1);
            d11 += __shfl_xor_sync(0xffffffffu, d11, 1);

            float z0 = fmaxf(d00 + b1A, 0.f) * w2A
                     + fmaxf(d01 + b1B, 0.f) * w2B;
            float z1 = fmaxf(d10 + b1A, 0.f) * w2A
                     + fmaxf(d11 + b1B, 0.f) * w2B;
#pragma unroll
            for (int off = 2; off <= 16; off <<= 1) {
                z0 += __shfl_xor_sync(0xffffffffu, z0, off);
                z1 += __shfl_xor_sync(0xffffffffu, z1, off);
            }
            if (lane == 0)
                red[rp][ooh] = make_float2(z0, z1);

            bar_sync(4, 128);     // fc-internal: red visible

            if (ft < 4) {
                const int r = ft;
                float2 v0 = red[r >> 1][0];
                float2 v1 = red[r >> 1][1];
                float s = (r & 1) ? (v0.y + v1.y) : (v0.x + v1.x);
                out[(size_t)(row0 + r) * T_ + (n - 1)] = sigmoid_fast(s + b2);
            }

            // stage xp(n+1) from long-ready carry regs; refill carry xp(n+2)
            if (n + 1 < T_) {
                float* Xw = Xp[(n + 1) & 1];
                Xw[0 * H_ + jcol] = xc0;
                Xw[1 * H_ + jcol] = xc1;
                Xw[2 * H_ + jcol] = xc2;
                Xw[3 * H_ + jcol] = xc3;
            }
            if (n + 2 < T_) {
                xc0 = __ldg(xs0); xs0 += H_;
                xc1 = __ldg(xs1); xs1 += H_;
                xc2 = __ldg(xs2); xs2 += H_;
                xc3 = __ldg(xs3); xs3 += H_;
            }

            bar_arrive((n & 1) ? 3 : 6, 256);   // fc(n) done
        }
    }
}

// ---------------------------------------------------------------------------

extern "C" void kernel_launch(void* const* d_in, const int* in_sizes, int n_in,
                              void* d_out, int out_size)
{
    const float* x     = (const float*)d_in[0];
    const float* W_ih  = (const float*)d_in[1];
    const float* W_hh  = (const float*)d_in[2];
    const float* b_ih  = (const float*)d_in[3];
    const float* b_hh  = (const float*)d_in[4];
    const float* fc1_w = (const float*)d_in[5];
    const float* fc1_b = (const float*)d_in[6];
    const float* fc2_w = (const float*)d_in[7];
    const float* fc2_b = (const float*)d_in[8];
    float* out = (float*)d_out;

    xp_kernel<<<(B_ * T_) / 256, 256>>>(x, W_ih, b_ih, b_hh);
    rnn_fused<<<128, NT>>>(W_hh, fc1_w, fc1_b, fc2_w, fc2_b, out);
}